// round 2
// baseline (speedup 1.0000x reference)
#include <cuda_runtime.h>

// MPM p2g scatter: 1M particles -> 128^3 grid of (mass, mom.x, mom.y, mom.z)
// Baseline: zero output, then per-particle 8-corner trilinear scatter via
// fp32 global atomics (REDG). Output fits in L2 (33.5MB < 126MB), so atomic
// traffic is L2-resident; expected bound = L2 atomic throughput.

static constexpr int NUM_POINTS = 1000000;
static constexpr int NUM_CELLS  = 128 * 128 * 128;
static constexpr float INV_CELL = 64.0f;

__global__ void zero_out_kernel(float4* __restrict__ out, int n4) {
    int i = blockIdx.x * blockDim.x + threadIdx.x;
    if (i < n4) out[i] = make_float4(0.f, 0.f, 0.f, 0.f);
}

__global__ __launch_bounds__(256) void p2g_scatter_kernel(
    const float* __restrict__ pos,
    const float* __restrict__ vel,
    const float* __restrict__ mass,
    float* __restrict__ out,
    int n)
{
    int i = blockIdx.x * blockDim.x + threadIdx.x;
    if (i >= n) return;

    // Particle data (12B each for pos/vel; coalesced enough at 3-stride f32).
    float px = pos[3 * i + 0];
    float py = pos[3 * i + 1];
    float pz = pos[3 * i + 2];
    float vx = vel[3 * i + 0];
    float vy = vel[3 * i + 1];
    float vz = vel[3 * i + 2];
    float m  = mass[i];

    float rx = px * INV_CELL;
    float ry = py * INV_CELL;
    float rz = pz * INV_CELL;
    float bx = floorf(rx), by = floorf(ry), bz = floorf(rz);
    int ix = (int)bx, iy = (int)by, iz = (int)bz;
    float fx = rx - bx, fy = ry - by, fz = rz - bz;

    // Trilinear weights: offset 0 -> (1-f), offset 1 -> f.
    // (Input guarantees all 8 corners in-range, so no validity mask needed.)
    float wx0 = 1.f - fx, wx1 = fx;
    float wy0 = 1.f - fy, wy1 = fy;
    float wz0 = 1.f - fz, wz1 = fz;

    // hash = z + x*128 + y*128*128
    int base = iz + (ix << 7) + (iy << 14);

    float wxy[4];
    wxy[0] = wx0 * wy0; // a=0,b=0
    wxy[1] = wx0 * wy1; // a=0,b=1
    wxy[2] = wx1 * wy0; // a=1,b=0
    wxy[3] = wx1 * wy1; // a=1,b=1
    int hoff[4];
    hoff[0] = base;
    hoff[1] = base + (1 << 14);
    hoff[2] = base + (1 << 7);
    hoff[3] = base + (1 << 7) + (1 << 14);

#pragma unroll
    for (int q = 0; q < 4; q++) {
        // z = 0 and z = 1 corners: adjacent cells -> adjacent 16B output slots.
        float s0 = wxy[q] * wz0 * m;
        float s1 = wxy[q] * wz1 * m;
        float* p = out + 4 * hoff[q];
        atomicAdd(p + 0, s0);
        atomicAdd(p + 1, s0 * vx);
        atomicAdd(p + 2, s0 * vy);
        atomicAdd(p + 3, s0 * vz);
        atomicAdd(p + 4, s1);
        atomicAdd(p + 5, s1 * vx);
        atomicAdd(p + 6, s1 * vy);
        atomicAdd(p + 7, s1 * vz);
    }
}

extern "C" void kernel_launch(void* const* d_in, const int* in_sizes, int n_in,
                              void* d_out, int out_size) {
    const float* pos  = (const float*)d_in[0];
    const float* vel  = (const float*)d_in[1];
    const float* mass = (const float*)d_in[2];
    float* out = (float*)d_out;

    int n4 = out_size / 4; // out_size = NUM_CELLS*4 floats -> NUM_CELLS float4s
    zero_out_kernel<<<(n4 + 255) / 256, 256>>>((float4*)out, n4);

    int n = in_sizes[2]; // mass count = NUM_POINTS
    p2g_scatter_kernel<<<(n + 255) / 256, 256>>>(pos, vel, mass, out, n);
}

// round 3
// speedup vs baseline: 2.4372x; 2.4372x over previous
#include <cuda_runtime.h>

// MPM p2g scatter: 1M particles -> 128^3 grid of (mass, mom.x, mom.y, mom.z)
// R2: replace 32 scalar fp32 atomicAdds per particle with 8 vectorized
// red.global.add.v4.f32 ops (one per stencil corner; the 4 output components
// of a cell are one contiguous 16B-aligned float4). 4x fewer L2 atomic ops.

static constexpr float INV_CELL = 64.0f;

__device__ __forceinline__ void red_add_v4(float* p, float a, float b, float c, float d) {
    asm volatile("red.global.add.v4.f32 [%0], {%1, %2, %3, %4};"
                 :: "l"(p), "f"(a), "f"(b), "f"(c), "f"(d)
                 : "memory");
}

__global__ void zero_out_kernel(float4* __restrict__ out, int n4) {
    int i = blockIdx.x * blockDim.x + threadIdx.x;
    if (i < n4) out[i] = make_float4(0.f, 0.f, 0.f, 0.f);
}

__global__ __launch_bounds__(256) void p2g_scatter_kernel(
    const float* __restrict__ pos,
    const float* __restrict__ vel,
    const float* __restrict__ mass,
    float* __restrict__ out,
    int n)
{
    int i = blockIdx.x * blockDim.x + threadIdx.x;
    if (i >= n) return;

    float px = pos[3 * i + 0];
    float py = pos[3 * i + 1];
    float pz = pos[3 * i + 2];
    float vx = vel[3 * i + 0];
    float vy = vel[3 * i + 1];
    float vz = vel[3 * i + 2];
    float m  = mass[i];

    float rx = px * INV_CELL;
    float ry = py * INV_CELL;
    float rz = pz * INV_CELL;
    float bx = floorf(rx), by = floorf(ry), bz = floorf(rz);
    int ix = (int)bx, iy = (int)by, iz = (int)bz;
    float fx = rx - bx, fy = ry - by, fz = rz - bz;

    // Trilinear weights: offset 0 -> (1-f), offset 1 -> f.
    // (Input guarantees all 8 corners in range; no validity mask needed.)
    float wx0 = 1.f - fx, wx1 = fx;
    float wy0 = 1.f - fy, wy1 = fy;
    float wz0 = 1.f - fz, wz1 = fz;

    // hash = z + x*128 + y*128*128
    int base = iz + (ix << 7) + (iy << 14);

    float wxy[4];
    wxy[0] = wx0 * wy0;
    wxy[1] = wx0 * wy1;
    wxy[2] = wx1 * wy0;
    wxy[3] = wx1 * wy1;
    int hoff[4];
    hoff[0] = base;
    hoff[1] = base + (1 << 14);
    hoff[2] = base + (1 << 7);
    hoff[3] = base + (1 << 7) + (1 << 14);

#pragma unroll
    for (int q = 0; q < 4; q++) {
        float s0 = wxy[q] * wz0 * m;
        float s1 = wxy[q] * wz1 * m;
        float* p = out + 4 * hoff[q];
        // z=0 corner: one 16B vector reduction (mass, mom.xyz)
        red_add_v4(p,     s0, s0 * vx, s0 * vy, s0 * vz);
        // z=1 corner: adjacent cell, next 16B slot
        red_add_v4(p + 4, s1, s1 * vx, s1 * vy, s1 * vz);
    }
}

extern "C" void kernel_launch(void* const* d_in, const int* in_sizes, int n_in,
                              void* d_out, int out_size) {
    const float* pos  = (const float*)d_in[0];
    const float* vel  = (const float*)d_in[1];
    const float* mass = (const float*)d_in[2];
    float* out = (float*)d_out;

    int n4 = out_size / 4;
    zero_out_kernel<<<(n4 + 255) / 256, 256>>>((float4*)out, n4);

    int n = in_sizes[2]; // mass count = NUM_POINTS
    p2g_scatter_kernel<<<(n + 255) / 256, 256>>>(pos, vel, mass, out, n);
}

// round 4
// speedup vs baseline: 3.2567x; 1.3362x over previous
#include <cuda_runtime.h>

// MPM p2g scatter: 1M particles -> 128^3 grid of (mass, mom.x, mom.y, mom.z)
// R3: kernel is at the LSU dispatch floor (1 op/cyc/SM). Cut load ops 4x by
// processing 4 particles/thread with float4 loads (28 scalar -> 7 vector
// loads per quad). REDGs stay at 8 v4 per particle (irreducible without
// binning, which loses at this particle density). Zeroing via memset node.

static constexpr float INV_CELL = 64.0f;

__device__ __forceinline__ void red_add_v4(float* p, float a, float b, float c, float d) {
    asm volatile("red.global.add.v4.f32 [%0], {%1, %2, %3, %4};"
                 :: "l"(p), "f"(a), "f"(b), "f"(c), "f"(d)
                 : "memory");
}

__device__ __forceinline__ void scatter_one(
    float px, float py, float pz,
    float vx, float vy, float vz,
    float m, float* __restrict__ out)
{
    float rx = px * INV_CELL;
    float ry = py * INV_CELL;
    float rz = pz * INV_CELL;
    float bx = floorf(rx), by = floorf(ry), bz = floorf(rz);
    int ix = (int)bx, iy = (int)by, iz = (int)bz;
    float fx = rx - bx, fy = ry - by, fz = rz - bz;

    float wx0 = 1.f - fx, wx1 = fx;
    float wy0 = 1.f - fy, wy1 = fy;
    float wz0 = 1.f - fz, wz1 = fz;

    // hash = z + x*128 + y*128*128 (all 8 corners guaranteed in range)
    int base = iz + (ix << 7) + (iy << 14);

    float wxy[4] = {wx0 * wy0, wx0 * wy1, wx1 * wy0, wx1 * wy1};
    int hoff[4] = {base, base + (1 << 14), base + (1 << 7), base + (1 << 7) + (1 << 14)};

#pragma unroll
    for (int q = 0; q < 4; q++) {
        float s0 = wxy[q] * wz0 * m;
        float s1 = wxy[q] * wz1 * m;
        float* p = out + 4 * hoff[q];
        red_add_v4(p,     s0, s0 * vx, s0 * vy, s0 * vz);
        red_add_v4(p + 4, s1, s1 * vx, s1 * vy, s1 * vz);
    }
}

__global__ __launch_bounds__(256) void p2g_scatter4_kernel(
    const float4* __restrict__ pos4,
    const float4* __restrict__ vel4,
    const float4* __restrict__ mass4,
    float* __restrict__ out,
    int n)   // particle count
{
    int t = blockIdx.x * blockDim.x + threadIdx.x;
    int p0 = 4 * t;
    if (p0 >= n) return;

    // 7 vector loads cover 4 particles (pos 3xf4, vel 3xf4, mass 1xf4).
    float4 pA = pos4[3 * t + 0];
    float4 pB = pos4[3 * t + 1];
    float4 pC = pos4[3 * t + 2];
    float4 vA = vel4[3 * t + 0];
    float4 vB = vel4[3 * t + 1];
    float4 vC = vel4[3 * t + 2];
    float4 mm = mass4[t];

    float P[12] = {pA.x, pA.y, pA.z, pA.w, pB.x, pB.y, pB.z, pB.w, pC.x, pC.y, pC.z, pC.w};
    float V[12] = {vA.x, vA.y, vA.z, vA.w, vB.x, vB.y, vB.z, vB.w, vC.x, vC.y, vC.z, vC.w};
    float M[4]  = {mm.x, mm.y, mm.z, mm.w};

    if (p0 + 3 < n) {
#pragma unroll
        for (int p = 0; p < 4; p++)
            scatter_one(P[3*p], P[3*p+1], P[3*p+2], V[3*p], V[3*p+1], V[3*p+2], M[p], out);
    } else {
#pragma unroll
        for (int p = 0; p < 4; p++)
            if (p0 + p < n)
                scatter_one(P[3*p], P[3*p+1], P[3*p+2], V[3*p], V[3*p+1], V[3*p+2], M[p], out);
    }
}

// Scalar fallback if particle count not divisible by 4 (vector casts invalid).
__global__ __launch_bounds__(256) void p2g_scatter1_kernel(
    const float* __restrict__ pos,
    const float* __restrict__ vel,
    const float* __restrict__ mass,
    float* __restrict__ out,
    int n)
{
    int i = blockIdx.x * blockDim.x + threadIdx.x;
    if (i >= n) return;
    scatter_one(pos[3*i], pos[3*i+1], pos[3*i+2],
                vel[3*i], vel[3*i+1], vel[3*i+2], mass[i], out);
}

extern "C" void kernel_launch(void* const* d_in, const int* in_sizes, int n_in,
                              void* d_out, int out_size) {
    const float* pos  = (const float*)d_in[0];
    const float* vel  = (const float*)d_in[1];
    const float* mass = (const float*)d_in[2];
    float* out = (float*)d_out;

    // Zero the accumulation grid (memset node in the graph; no alloc).
    cudaMemsetAsync(d_out, 0, (size_t)out_size * sizeof(float));

    int n = in_sizes[2]; // mass count = NUM_POINTS
    if ((n & 3) == 0) {
        int nq = n / 4;
        p2g_scatter4_kernel<<<(nq + 255) / 256, 256>>>(
            (const float4*)pos, (const float4*)vel, (const float4*)mass, out, n);
    } else {
        p2g_scatter1_kernel<<<(n + 255) / 256, 256>>>(pos, vel, mass, out, n);
    }
}

// round 5
// speedup vs baseline: 3.6196x; 1.1114x over previous
#include <cuda_runtime.h>

// MPM p2g scatter: 1M particles -> 128^3 grid of (mass, mom.x, mom.y, mom.z)
// R4: corner-parallel layout. The binding resource is L1tex wavefronts from
// scattered REDG.128s. A particle's 8 corners span only ~4.5 distinct 128B
// lines (z-pairs are 16B apart), so putting all 8 corners of a particle in
// the SAME warp instruction (8 lanes/particle, 4 particles/warp-instr) lets
// the L1 coalescer merge them: ~18 wavefronts per warp REDG instead of 32.
// Loads become 8-way-broadcast scalars (cheap, ~1 wavefront each); weight
// math is computed redundantly per lane (ALU/FMA pipes are nearly idle).

static constexpr float INV_CELL = 64.0f;

__device__ __forceinline__ void red_add_v4(float* p, float a, float b, float c, float d) {
    asm volatile("red.global.add.v4.f32 [%0], {%1, %2, %3, %4};"
                 :: "l"(p), "f"(a), "f"(b), "f"(c), "f"(d)
                 : "memory");
}

__global__ __launch_bounds__(256) void p2g_corner_kernel(
    const float* __restrict__ pos,
    const float* __restrict__ vel,
    const float* __restrict__ mass,
    float* __restrict__ out,
    int n)
{
    int warp_id = (blockIdx.x * blockDim.x + threadIdx.x) >> 5;
    int lane = threadIdx.x & 31;
    int p_local = lane >> 3;      // which of 4 particles in this sub-iteration
    int c = lane & 7;             // corner id: bit0=z, bit1=x, bit2=y
    int cz = c & 1;
    int cx = (c >> 1) & 1;
    int cy = (c >> 2) & 1;

    int base = warp_id * 32;      // 32 particles per warp (8 sub-iterations x 4)

#pragma unroll
    for (int s = 0; s < 8; s++) {
        int pidx = base + s * 4 + p_local;
        if (pidx < n) {
            // 8 lanes share each particle's data -> broadcast loads,
            // 4 particles per warp instruction span <=48B -> ~1 wavefront each.
            float px = pos[3 * pidx + 0];
            float py = pos[3 * pidx + 1];
            float pz = pos[3 * pidx + 2];
            float vx = vel[3 * pidx + 0];
            float vy = vel[3 * pidx + 1];
            float vz = vel[3 * pidx + 2];
            float m  = mass[pidx];

            float rx = px * INV_CELL;
            float ry = py * INV_CELL;
            float rz = pz * INV_CELL;
            float bx = floorf(rx), by = floorf(ry), bz = floorf(rz);
            float fx = rx - bx, fy = ry - by, fz = rz - bz;

            // This lane's corner weight (offset 0 -> 1-f, offset 1 -> f).
            float wxv = cx ? fx : 1.f - fx;
            float wyv = cy ? fy : 1.f - fy;
            float wzv = cz ? fz : 1.f - fz;

            // hash = z + x*128 + y*128*128 (all corners guaranteed in range)
            int hash = ((int)bz + cz) + (((int)bx + cx) << 7) + (((int)by + cy) << 14);

            float sm = wxv * wyv * wzv * m;
            // One 16B vector reduction per corner; the warp's 32 lanes cover
            // 4 particles x 8 corners hitting ~18 distinct L2/L1 lines.
            red_add_v4(out + 4 * hash, sm, sm * vx, sm * vy, sm * vz);
        }
    }
}

extern "C" void kernel_launch(void* const* d_in, const int* in_sizes, int n_in,
                              void* d_out, int out_size) {
    const float* pos  = (const float*)d_in[0];
    const float* vel  = (const float*)d_in[1];
    const float* mass = (const float*)d_in[2];
    float* out = (float*)d_out;

    // Zero the accumulation grid (memset node in the graph; no alloc).
    cudaMemsetAsync(d_out, 0, (size_t)out_size * sizeof(float));

    int n = in_sizes[2];                     // mass count = NUM_POINTS
    int warps = (n + 31) / 32;               // 32 particles per warp
    int threads_total = warps * 32;
    int blocks = (threads_total + 255) / 256;
    p2g_corner_kernel<<<blocks, 256>>>(pos, vel, mass, out, n);
}

// round 6
// speedup vs baseline: 3.7593x; 1.0386x over previous
#include <cuda_runtime.h>

// MPM p2g scatter: 1M particles -> 128^3 grid of (mass, mom.x, mom.y, mom.z)
// R5: corner-parallel REDG scatter (R4) + warp-cooperative vectorized loads
// staged through shared memory. The L1tex wavefront pipeline is the binding
// resource; REDG line-touches (4.5/particle) are the scatter floor, so this
// round removes the remaining ~25% of L1tex work: 56 broadcast scalar LDGs
// per 32 particles become 3 coalesced LDG.128 warp instructions (~12 wf),
// with the compute loop reading particle data via conflict-free broadcast
// LDS off the smem crossbar instead of the tagged-L1 path.

static constexpr float INV_CELL = 64.0f;

__device__ __forceinline__ void red_add_v4(float* p, float a, float b, float c, float d) {
    asm volatile("red.global.add.v4.f32 [%0], {%1, %2, %3, %4};"
                 :: "l"(p), "f"(a), "f"(b), "f"(c), "f"(d)
                 : "memory");
}

// Per-warp staging: pos[96] | vel[96] | mass[32] floats = 224 floats (896B).
static constexpr int WARP_STAGE = 224;

__global__ __launch_bounds__(256) void p2g_corner_kernel(
    const float* __restrict__ pos,
    const float* __restrict__ vel,
    const float* __restrict__ mass,
    float* __restrict__ out,
    int n)
{
    __shared__ float stage[8 * WARP_STAGE];   // 8 warps/block

    int warp_id = (blockIdx.x * blockDim.x + threadIdx.x) >> 5;  // global warp
    int lane = threadIdx.x & 31;
    int wib = threadIdx.x >> 5;               // warp in block
    float* sp = stage + wib * WARP_STAGE;     // [0,96) pos, [96,192) vel, [192,224) mass

    int base = warp_id * 32;                  // 32 particles per warp
    if (base >= n) return;

    // ---- cooperative load: 3 coalesced LDG.128 instructions per warp ----
    if (base + 32 <= n) {
        const float4* pos4 = (const float4*)pos;
        const float4* vel4 = (const float4*)vel;
        const float4* mass4 = (const float4*)mass;
        if (lane < 24) {
            ((float4*)sp)[lane]        = pos4[warp_id * 24 + lane];   // 96 floats
            ((float4*)(sp + 96))[lane] = vel4[warp_id * 24 + lane];   // 96 floats
        } else {
            ((float4*)(sp + 192))[lane - 24] = mass4[warp_id * 8 + (lane - 24)]; // 32 floats
        }
    } else {
        // tail warp: scalar guarded loads (rare path)
        int nv = n - base;                    // 1..31 valid particles
        for (int e = lane; e < nv * 3; e += 32) {
            sp[e]      = pos[base * 3 + e];
            sp[96 + e] = vel[base * 3 + e];
        }
        if (lane < nv) sp[192 + lane] = mass[base + lane];
    }
    __syncwarp();

    // ---- corner-parallel scatter: 8 lanes/particle, 4 particles/instr ----
    int p_local = lane >> 3;                  // particle within sub-iteration
    int c = lane & 7;                         // corner: bit0=z, bit1=x, bit2=y
    int cz = c & 1;
    int cx = (c >> 1) & 1;
    int cy = (c >> 2) & 1;

#pragma unroll
    for (int s = 0; s < 8; s++) {
        int idx = s * 4 + p_local;            // particle index within warp
        if (base + idx < n) {
            // broadcast LDS (conflict-free: 4 distinct banks, 8-way bcast)
            float px = sp[3 * idx + 0];
            float py = sp[3 * idx + 1];
            float pz = sp[3 * idx + 2];
            float vx = sp[96 + 3 * idx + 0];
            float vy = sp[96 + 3 * idx + 1];
            float vz = sp[96 + 3 * idx + 2];
            float m  = sp[192 + idx];

            float rx = px * INV_CELL;
            float ry = py * INV_CELL;
            float rz = pz * INV_CELL;
            float bx = floorf(rx), by = floorf(ry), bz = floorf(rz);
            float fx = rx - bx, fy = ry - by, fz = rz - bz;

            float wxv = cx ? fx : 1.f - fx;
            float wyv = cy ? fy : 1.f - fy;
            float wzv = cz ? fz : 1.f - fz;

            // hash = z + x*128 + y*128*128 (all corners guaranteed in range)
            int hash = ((int)bz + cz) + (((int)bx + cx) << 7) + (((int)by + cy) << 14);

            float sm = wxv * wyv * wzv * m;
            red_add_v4(out + 4 * hash, sm, sm * vx, sm * vy, sm * vz);
        }
    }
}

extern "C" void kernel_launch(void* const* d_in, const int* in_sizes, int n_in,
                              void* d_out, int out_size) {
    const float* pos  = (const float*)d_in[0];
    const float* vel  = (const float*)d_in[1];
    const float* mass = (const float*)d_in[2];
    float* out = (float*)d_out;

    // Zero the accumulation grid (memset node in the graph; no alloc).
    cudaMemsetAsync(d_out, 0, (size_t)out_size * sizeof(float));

    int n = in_sizes[2];                     // mass count = NUM_POINTS
    int warps = (n + 31) / 32;               // 32 particles per warp
    int blocks = (warps + 7) / 8;            // 8 warps (256 threads) per block
    p2g_corner_kernel<<<blocks, 256>>>(pos, vel, mass, out, n);
}